// round 1
// baseline (speedup 1.0000x reference)
#include <cuda_runtime.h>
#include <math.h>

// Problem constants
#define TOK   4096      // B*S
#define SEQ   2048
#define DM    512
#define DQKV  1536
#define DFF   2048
#define NB    2
#define NH    8

// ---------------- scratch (no allocations allowed) ----------------
__device__ float g_Z[TOK * DM];
__device__ float g_QKV[TOK * DQKV];
__device__ float g_ATT[TOK * DM];
__device__ float g_Y[TOK * DM];
__device__ float g_H[TOK * DFF];
__device__ float g_Wqkv[DM * DQKV];
__device__ float g_bqkv[DQKV];

// ---------------- weight repack: [H,D,dh] x3 -> [D, 3*H*dh] ----------------
__global__ void pack_qkv_kernel(const float* __restrict__ Wq,
                                const float* __restrict__ Wk,
                                const float* __restrict__ Wv,
                                const float* __restrict__ bq,
                                const float* __restrict__ bk,
                                const float* __restrict__ bv,
                                float* __restrict__ Wp,
                                float* __restrict__ bp)
{
    int idx = blockIdx.x * blockDim.x + threadIdx.x;
    if (idx < DQKV) {
        bp[idx] = (idx < 512) ? bq[idx] : (idx < 1024 ? bk[idx - 512] : bv[idx - 1024]);
    }
    if (idx >= DM * DQKV) return;
    int d = idx / DQKV;
    int j = idx % DQKV;
    const float* W = (j < 512) ? Wq : (j < 1024 ? Wk : Wv);
    int jj = j & 511;
    int h = jj >> 6, e = jj & 63;
    Wp[idx] = W[((size_t)h * DM + d) * 64 + e];
}

// ---------------- SGEMM 128x128x16, 256 threads, 8x8 microtile ----------------
// C[M,N] = A[M,K] * B[K,N] + bias[N] (+ R[M,N]) (optionally relu)
// All of M,N divisible by 128, K divisible by 16 here.
__global__ __launch_bounds__(256) void gemm_kernel(
    const float* __restrict__ A, const float* __restrict__ B,
    const float* __restrict__ bias, const float* __restrict__ R,
    float* __restrict__ C, int M, int N, int K, int doRelu)
{
    __shared__ float As[16][128];
    __shared__ float Bs[16][128];
    int tid  = threadIdx.x;
    int bm   = blockIdx.y << 7;
    int bn   = blockIdx.x << 7;
    int tidm = tid >> 4, tidn = tid & 15;

    float acc[8][8];
#pragma unroll
    for (int i = 0; i < 8; i++)
#pragma unroll
        for (int j = 0; j < 8; j++) acc[i][j] = 0.f;

    for (int k0 = 0; k0 < K; k0 += 16) {
#pragma unroll
        for (int i = 0; i < 2; i++) {
            int idx = tid + (i << 8);
            int m = idx >> 2, kk = (idx & 3) << 2;
            float4 a = *(const float4*)(A + (size_t)(bm + m) * K + k0 + kk);
            As[kk + 0][m] = a.x; As[kk + 1][m] = a.y;
            As[kk + 2][m] = a.z; As[kk + 3][m] = a.w;
        }
#pragma unroll
        for (int i = 0; i < 2; i++) {
            int idx = tid + (i << 8);
            int kk = idx >> 5, n4 = (idx & 31) << 2;
            *(float4*)(&Bs[kk][n4]) =
                *(const float4*)(B + (size_t)(k0 + kk) * N + bn + n4);
        }
        __syncthreads();
#pragma unroll
        for (int k = 0; k < 16; k++) {
            float a[8], bb[8];
            *(float4*)(a)      = *(const float4*)(&As[k][tidm << 3]);
            *(float4*)(a + 4)  = *(const float4*)(&As[k][(tidm << 3) + 4]);
            *(float4*)(bb)     = *(const float4*)(&Bs[k][tidn << 3]);
            *(float4*)(bb + 4) = *(const float4*)(&Bs[k][(tidn << 3) + 4]);
#pragma unroll
            for (int i = 0; i < 8; i++)
#pragma unroll
                for (int j = 0; j < 8; j++)
                    acc[i][j] = fmaf(a[i], bb[j], acc[i][j]);
        }
        __syncthreads();
    }

#pragma unroll
    for (int i = 0; i < 8; i++) {
        int row = bm + (tidm << 3) + i;
#pragma unroll
        for (int jh = 0; jh < 2; jh++) {
            int col = bn + (tidn << 3) + (jh << 2);
            float4 o;
            o.x = acc[i][jh * 4 + 0]; o.y = acc[i][jh * 4 + 1];
            o.z = acc[i][jh * 4 + 2]; o.w = acc[i][jh * 4 + 3];
            float4 bv = *(const float4*)(bias + col);
            o.x += bv.x; o.y += bv.y; o.z += bv.z; o.w += bv.w;
            if (R) {
                float4 rv = *(const float4*)(R + (size_t)row * N + col);
                o.x += rv.x; o.y += rv.y; o.z += rv.z; o.w += rv.w;
            }
            if (doRelu) {
                o.x = fmaxf(o.x, 0.f); o.y = fmaxf(o.y, 0.f);
                o.z = fmaxf(o.z, 0.f); o.w = fmaxf(o.w, 0.f);
            }
            *(float4*)(C + (size_t)row * N + col) = o;
        }
    }
}

// ---------------- fused flash attention ----------------
// grid (S/64, H, B), 256 threads; Bq=64 queries, Tk=64 keys/tile, d=64
#define AP 65   // smem pitch to avoid column-read bank conflicts
__global__ __launch_bounds__(256) void attn_kernel(const float* __restrict__ QKV,
                                                   float* __restrict__ O)
{
    extern __shared__ float sm[];
    float* Qs   = sm;                 // 64*AP
    float* Ks   = Qs + 64 * AP;
    float* Vs   = Ks + 64 * AP;
    float* Ps   = Vs + 64 * AP;       // 64*64
    float* mrow = Ps + 64 * 64;       // 64
    float* lrow = mrow + 64;          // 64
    float* frow = lrow + 64;          // 64

    int h  = blockIdx.y, b = blockIdx.z;
    int q0 = blockIdx.x * 64;
    const float* base = QKV + (size_t)b * SEQ * DQKV + h * 64;
    int tid  = threadIdx.x;
    int tidm = tid >> 4, tidn = tid & 15;
    int r0 = tidm << 2, c0 = tidn << 2;

    // load Q tile (pre-scaled by 1/sqrt(d) = 0.125, exact power of two)
    for (int i = tid; i < 1024; i += 256) {
        int r = i >> 4, c4 = (i & 15) << 2;
        float4 t4 = *(const float4*)(base + (size_t)(q0 + r) * DQKV + c4);
        float* d = Qs + r * AP + c4;
        d[0] = t4.x * 0.125f; d[1] = t4.y * 0.125f;
        d[2] = t4.z * 0.125f; d[3] = t4.w * 0.125f;
    }
    if (tid < 64) { mrow[tid] = -1e30f; lrow[tid] = 0.f; }
    float acc[4][4];
#pragma unroll
    for (int i = 0; i < 4; i++)
#pragma unroll
        for (int j = 0; j < 4; j++) acc[i][j] = 0.f;
    __syncthreads();

    for (int s0 = 0; s0 < SEQ; s0 += 64) {
        for (int i = tid; i < 1024; i += 256) {
            int r = i >> 4, c4 = (i & 15) << 2;
            const float* gk = base + 512 + (size_t)(s0 + r) * DQKV + c4;
            float4 kv = *(const float4*)gk;
            float4 vv = *(const float4*)(gk + 512);
            float* dk = Ks + r * AP + c4;
            float* dv = Vs + r * AP + c4;
            dk[0] = kv.x; dk[1] = kv.y; dk[2] = kv.z; dk[3] = kv.w;
            dv[0] = vv.x; dv[1] = vv.y; dv[2] = vv.z; dv[3] = vv.w;
        }
        __syncthreads();

        // S = Q K^T (scale already in Q)
        float sc[4][4];
#pragma unroll
        for (int i = 0; i < 4; i++)
#pragma unroll
            for (int j = 0; j < 4; j++) sc[i][j] = 0.f;
#pragma unroll 8
        for (int e = 0; e < 64; e++) {
            float qa[4], kb[4];
#pragma unroll
            for (int i = 0; i < 4; i++) qa[i] = Qs[(r0 + i) * AP + e];
#pragma unroll
            for (int j = 0; j < 4; j++) kb[j] = Ks[(c0 + j) * AP + e];
#pragma unroll
            for (int i = 0; i < 4; i++)
#pragma unroll
                for (int j = 0; j < 4; j++)
                    sc[i][j] = fmaf(qa[i], kb[j], sc[i][j]);
        }
#pragma unroll
        for (int i = 0; i < 4; i++)
#pragma unroll
            for (int j = 0; j < 4; j++)
                Ps[(r0 + i) * 64 + c0 + j] = sc[i][j];
        __syncthreads();

        // online softmax: one thread per row
        if (tid < 64) {
            float mold = mrow[tid];
            float mx = mold;
            float* pr = Ps + tid * 64;
#pragma unroll 8
            for (int c = 0; c < 64; c++) mx = fmaxf(mx, pr[c]);
            float f = __expf(mold - mx);
            float sum = 0.f;
#pragma unroll 8
            for (int c = 0; c < 64; c++) {
                float p = __expf(pr[c] - mx);
                pr[c] = p;
                sum += p;
            }
            mrow[tid] = mx;
            lrow[tid] = lrow[tid] * f + sum;
            frow[tid] = f;
        }
        __syncthreads();

        // rescale accumulators + acc += P V
        float fr[4];
#pragma unroll
        for (int i = 0; i < 4; i++) fr[i] = frow[r0 + i];
#pragma unroll
        for (int i = 0; i < 4; i++)
#pragma unroll
            for (int j = 0; j < 4; j++) acc[i][j] *= fr[i];
#pragma unroll 8
        for (int c = 0; c < 64; c++) {
            float p[4], vv[4];
#pragma unroll
            for (int i = 0; i < 4; i++) p[i] = Ps[(r0 + i) * 64 + c];
#pragma unroll
            for (int j = 0; j < 4; j++) vv[j] = Vs[c * AP + c0 + j];
#pragma unroll
            for (int i = 0; i < 4; i++)
#pragma unroll
                for (int j = 0; j < 4; j++)
                    acc[i][j] = fmaf(p[i], vv[j], acc[i][j]);
        }
        __syncthreads();
    }

    float linv[4];
#pragma unroll
    for (int i = 0; i < 4; i++) linv[i] = 1.0f / lrow[r0 + i];
#pragma unroll
    for (int i = 0; i < 4; i++)
#pragma unroll
        for (int j = 0; j < 4; j++)
            O[(size_t)(b * SEQ + q0 + r0 + i) * DM + h * 64 + c0 + j] =
                acc[i][j] * linv[i];
}

// ---------------- layernorm over D=512, one block per row ----------------
__global__ __launch_bounds__(128) void ln_kernel(const float* __restrict__ X,
                                                 const float* __restrict__ gamma,
                                                 const float* __restrict__ beta,
                                                 float* __restrict__ Out)
{
    int row = blockIdx.x;
    int t = threadIdx.x;
    const float4 v = *(const float4*)(X + (size_t)row * DM + t * 4);
    float s  = v.x + v.y + v.z + v.w;
    float ss = v.x * v.x + v.y * v.y + v.z * v.z + v.w * v.w;
    int lane = t & 31, wid = t >> 5;
#pragma unroll
    for (int o = 16; o; o >>= 1) {
        s  += __shfl_down_sync(0xffffffffu, s, o);
        ss += __shfl_down_sync(0xffffffffu, ss, o);
    }
    __shared__ float rs[4], rq[4];
    if (!lane) { rs[wid] = s; rq[wid] = ss; }
    __syncthreads();
    s  = rs[0] + rs[1] + rs[2] + rs[3];
    ss = rq[0] + rq[1] + rq[2] + rq[3];
    float mu  = s * (1.0f / DM);
    float var = ss * (1.0f / DM) - mu * mu;
    float inv = rsqrtf(var + 1e-5f);
    float4 g4 = *(const float4*)(gamma + t * 4);
    float4 b4 = *(const float4*)(beta + t * 4);
    float4 o;
    o.x = (v.x - mu) * inv * g4.x + b4.x;
    o.y = (v.y - mu) * inv * g4.y + b4.y;
    o.z = (v.z - mu) * inv * g4.z + b4.z;
    o.w = (v.w - mu) * inv * g4.w + b4.w;
    *(float4*)(Out + (size_t)row * DM + t * 4) = o;
}

// ---------------- driver ----------------
extern "C" void kernel_launch(void* const* d_in, const int* in_sizes, int n_in,
                              void* d_out, int out_size)
{
    const float* z   = (const float*)d_in[0];
    const float* Wq  = (const float*)d_in[1];
    const float* bq  = (const float*)d_in[2];
    const float* Wk  = (const float*)d_in[3];
    const float* bk  = (const float*)d_in[4];
    const float* Wv  = (const float*)d_in[5];
    const float* bv  = (const float*)d_in[6];
    const float* Wo  = (const float*)d_in[7];
    const float* bo  = (const float*)d_in[8];
    const float* W1  = (const float*)d_in[9];
    const float* b1  = (const float*)d_in[10];
    const float* W2  = (const float*)d_in[11];
    const float* b2  = (const float*)d_in[12];
    const float* g1  = (const float*)d_in[13];
    const float* be1 = (const float*)d_in[14];
    const float* g2  = (const float*)d_in[15];
    const float* be2 = (const float*)d_in[16];
    float* out = (float*)d_out;

    float *Z, *QKV, *ATT, *Y, *Hb, *Wqkv, *bqkv;
    cudaGetSymbolAddress((void**)&Z,    g_Z);
    cudaGetSymbolAddress((void**)&QKV,  g_QKV);
    cudaGetSymbolAddress((void**)&ATT,  g_ATT);
    cudaGetSymbolAddress((void**)&Y,    g_Y);
    cudaGetSymbolAddress((void**)&Hb,   g_H);
    cudaGetSymbolAddress((void**)&Wqkv, g_Wqkv);
    cudaGetSymbolAddress((void**)&bqkv, g_bqkv);

    const int attn_smem = (3 * 64 * AP + 64 * 64 + 3 * 64) * (int)sizeof(float); // 67072
    cudaFuncSetAttribute(attn_kernel, cudaFuncAttributeMaxDynamicSharedMemorySize,
                         attn_smem);

    cudaMemcpyAsync(Z, z, sizeof(float) * TOK * DM, cudaMemcpyDeviceToDevice, 0);
    pack_qkv_kernel<<<(DM * DQKV + 255) / 256, 256>>>(Wq, Wk, Wv, bq, bk, bv,
                                                      Wqkv, bqkv);

    for (int it = 0; it < 4; it++) {
        // QKV projection: [4096,512] x [512,1536]
        gemm_kernel<<<dim3(DQKV / 128, TOK / 128), 256>>>(
            Z, Wqkv, bqkv, nullptr, QKV, TOK, DQKV, DM, 0);
        // attention
        attn_kernel<<<dim3(SEQ / 64, NH, NB), 256, attn_smem>>>(QKV, ATT);
        // output projection + residual
        gemm_kernel<<<dim3(DM / 128, TOK / 128), 256>>>(
            ATT, Wo, bo, Z, Y, TOK, DM, DM, 0);
        // LN1 -> z (or final output on last iteration)
        float* lnout = (it == 3) ? out : Z;
        ln_kernel<<<TOK, 128>>>(Y, g1, be1, lnout);
        if (it == 3) break;   // z_refined is post-LN1 of last iter; FFN unused
        // FFN
        gemm_kernel<<<dim3(DFF / 128, TOK / 128), 256>>>(
            Z, W1, b1, nullptr, Hb, TOK, DFF, DM, 1);
        gemm_kernel<<<dim3(DM / 128, TOK / 128), 256>>>(
            Hb, W2, b2, Z, Y, TOK, DM, DFF, 0);
        ln_kernel<<<TOK, 128>>>(Y, g2, be2, Z);
    }
}